// round 14
// baseline (speedup 1.0000x reference)
#include <cuda_runtime.h>
#include <cuda_fp16.h>
#include <cstdint>

// ---------------------------------------------------------------------------
// RNNT joiner, two-pass (R7 frozen config; R14 = single issue-order change):
//   pass 1: Ah[m][d] = fp16(relu(src[b,t,d] + tgt[b,u,d]))
//   pass 2: out = Ah @ Wh^T + bias  (M=65536, N=1024, K=1024, HMMA fp16)
// GEMM: 512 thr, 16 warps (4m x 4n of 32x32), CTA 128x128x32, 4-stage
// cp.async, PITCH=80, 2 CTAs/SM (32 warps), nt-fast grid.
// R14 change (only): cp.async prefetch issued at END of the k-iteration,
// off the post-barrier LDSM->HMMA critical path. Group counts, barriers,
// and slot-reuse safety identical to R7/R13.
// ---------------------------------------------------------------------------

#define B_ 4
#define T_ 256
#define U_ 64
#define D_ 1024
#define V_ 1024
#define M_ (B_ * T_ * U_)

#define TILE_M 128
#define TILE_N 128
#define TILE_K 32
#define KITERS (D_ / TILE_K) /* 32 */
#define NTHREADS 512
#define NSTAGE 4

#define PITCH 80                      /* 64B row + 16B pad: conflict-free ldmatrix */
#define STAGE_BYTES (128 * PITCH)     /* 10240 */
#define SMEM_DYN (2 * NSTAGE * STAGE_BYTES) /* A[4] + B[4] = 81920 -> 2 CTAs/SM */

__device__ __forceinline__ uint32_t smem_u32(const void* p) {
    uint32_t a;
    asm("{ .reg .u64 t; cvta.to.shared.u64 t, %1; cvt.u32.u64 %0, t; }" : "=r"(a) : "l"(p));
    return a;
}

__device__ __forceinline__ void cp16(uint32_t saddr, const void* g) {
    asm volatile("cp.async.cg.shared.global [%0], [%1], 16;" :: "r"(saddr), "l"(g) : "memory");
}
#define CP_COMMIT() asm volatile("cp.async.commit_group;" ::: "memory")
#define CP_WAIT(n)  asm volatile("cp.async.wait_group %0;" :: "n"(n) : "memory")

__device__ __forceinline__ void ldsm_x4(uint32_t (&r)[4], uint32_t addr) {
    asm volatile("ldmatrix.sync.aligned.m8n8.x4.shared.b16 {%0,%1,%2,%3}, [%4];"
                 : "=r"(r[0]), "=r"(r[1]), "=r"(r[2]), "=r"(r[3]) : "r"(addr));
}

__device__ __forceinline__ void mma16816(float (&d)[4], const uint32_t (&a)[4],
                                         uint32_t b0, uint32_t b1) {
    asm volatile(
        "mma.sync.aligned.m16n8k16.row.col.f32.f16.f16.f32 "
        "{%0,%1,%2,%3}, {%4,%5,%6,%7}, {%8,%9}, {%0,%1,%2,%3};"
        : "+f"(d[0]), "+f"(d[1]), "+f"(d[2]), "+f"(d[3])
        : "r"(a[0]), "r"(a[1]), "r"(a[2]), "r"(a[3]), "r"(b0), "r"(b1));
}

__device__ __forceinline__ uint32_t h2u(__half2 h) { return *reinterpret_cast<uint32_t*>(&h); }

// Static scratch: W in fp16 (2 MB) and the materialized A operand (128 MB fp16).
__device__ __align__(16) __half g_Wh[(size_t)V_ * D_];
__device__ __align__(16) __half g_Ah[(size_t)M_ * D_];

// convert W + write the appended lengths tail
__global__ void __launch_bounds__(256) prep_kernel(
    const float* __restrict__ W,
    const int* __restrict__ sl, const int* __restrict__ tl,
    float* __restrict__ tail_out, int ntail) {
    int i = blockIdx.x * blockDim.x + threadIdx.x;  // over V*D/4
    float4 v = reinterpret_cast<const float4*>(W)[i];
    __half2* dst = reinterpret_cast<__half2*>(g_Wh);
    dst[2 * i + 0] = __floats2half2_rn(v.x, v.y);
    dst[2 * i + 1] = __floats2half2_rn(v.z, v.w);
    if (blockIdx.x == 0 && threadIdx.x < (unsigned)ntail) {
        int k = threadIdx.x;
        int val = (k < B_) ? sl[k] : ((k < 2 * B_) ? tl[k - B_] : 0);
        tail_out[k] = (float)val;
    }
}

// pass 1: Ah = fp16(relu(src+tgt)); 8 elements per thread (coalesced 16B/lane)
__global__ void __launch_bounds__(256) build_A(const float* __restrict__ src,
                                               const float* __restrict__ tgt) {
    size_t i = (size_t)blockIdx.x * blockDim.x + threadIdx.x;  // over M*D/8
    int dc = (int)(i & (D_ / 8 - 1)) * 8;
    size_t row = i >> 7;
    int u = (int)(row & (U_ - 1));
    int t = (int)((row >> 6) & (T_ - 1));
    int b = (int)(row >> 14);
    const float4* sp = reinterpret_cast<const float4*>(src + ((size_t)(b * T_ + t)) * D_ + dc);
    const float4* tp = reinterpret_cast<const float4*>(tgt + ((size_t)(b * U_ + u)) * D_ + dc);
    float4 s0 = sp[0], s1 = sp[1];
    float4 g0 = tp[0], g1 = tp[1];
    __half2 h0 = __floats2half2_rn(fmaxf(s0.x + g0.x, 0.f), fmaxf(s0.y + g0.y, 0.f));
    __half2 h1 = __floats2half2_rn(fmaxf(s0.z + g0.z, 0.f), fmaxf(s0.w + g0.w, 0.f));
    __half2 h2 = __floats2half2_rn(fmaxf(s1.x + g1.x, 0.f), fmaxf(s1.y + g1.y, 0.f));
    __half2 h3 = __floats2half2_rn(fmaxf(s1.z + g1.z, 0.f), fmaxf(s1.w + g1.w, 0.f));
    *reinterpret_cast<uint4*>(g_Ah + row * D_ + dc) =
        make_uint4(h2u(h0), h2u(h1), h2u(h2), h2u(h3));
}

__global__ void __launch_bounds__(NTHREADS, 2) joiner_gemm(
    const float* __restrict__ bias, float* __restrict__ out) {
    extern __shared__ __align__(128) char smem[];
    const uint32_t A0 = smem_u32(smem);
    const uint32_t Bb0 = A0 + NSTAGE * STAGE_BYTES;

    const int tid = threadIdx.x;
    const int wid = tid >> 5, lane = tid & 31;
    const int nt = blockIdx.x;   // 0..7   (nt-fast: 8 CTAs share one A tile in L2)
    const int mt = blockIdx.y;   // 0..511

    // ---- load-role: thread -> (row = tid>>2, seg = tid&3); 1 cp16 per tile ----
    const int lrow = tid >> 2;
    const int lseg = tid & 3;
    const __half* arow = g_Ah + ((size_t)(mt * TILE_M + lrow)) * D_ + lseg * 8;
    const __half* wrow = g_Wh + ((size_t)(nt * TILE_N + lrow)) * D_ + lseg * 8;
    const uint32_t fill_off = (uint32_t)lrow * PITCH + lseg * 16;

    // ---- mma-role: 16 warps = 4m x 4n, warp tile 32x32 ----
    const int m0w = (wid & 3) * 32;
    const int n0w = (wid >> 2) * 32;
    const uint32_t a_ld_off = (uint32_t)(m0w + (lane & 15)) * PITCH + (lane >> 4) * 16;
    const uint32_t b_ld_off =
        (uint32_t)(n0w + (lane & 7) + ((lane & 16) >> 1)) * PITCH + ((lane >> 3) & 1) * 16;

    float acc[2][4][4];
#pragma unroll
    for (int mi = 0; mi < 2; mi++)
#pragma unroll
        for (int ni = 0; ni < 4; ni++)
#pragma unroll
            for (int q = 0; q < 4; q++) acc[mi][ni][q] = 0.f;

    auto loadStage = [&](int s, int kt) {
        cp16(A0 + s * STAGE_BYTES + fill_off, arow + kt * TILE_K);
        cp16(Bb0 + s * STAGE_BYTES + fill_off, wrow + kt * TILE_K);
    };

    // prologue: stages 0,1,2 in flight
#pragma unroll
    for (int s = 0; s < NSTAGE - 1; s++) {
        loadStage(s, s);
        CP_COMMIT();
    }

#pragma unroll 1
    for (int kt = 0; kt < KITERS; kt++) {
        const int cur = kt & (NSTAGE - 1);
        CP_WAIT(2);          // stage `cur` complete (own groups); barrier makes global
        __syncthreads();

        const uint32_t Ab = A0 + cur * STAGE_BYTES;
        const uint32_t Bt = Bb0 + cur * STAGE_BYTES;
#pragma unroll
        for (int k16 = 0; k16 < 2; k16++) {
            const uint32_t kb = k16 * 32;
            uint32_t bfr[2][4];
            ldsm_x4(bfr[0], Bt + b_ld_off + kb);
            ldsm_x4(bfr[1], Bt + 16u * PITCH + b_ld_off + kb);
            uint32_t afr[2][4];
            ldsm_x4(afr[0], Ab + a_ld_off + kb);
            ldsm_x4(afr[1], Ab + 16u * PITCH + a_ld_off + kb);
#pragma unroll
            for (int mi = 0; mi < 2; mi++)
#pragma unroll
                for (int ni = 0; ni < 4; ni++)
                    mma16816(acc[mi][ni], afr[mi], bfr[ni >> 1][(ni & 1) * 2],
                             bfr[ni >> 1][(ni & 1) * 2 + 1]);
        }

        // R14: prefetch issued off the critical path, after the MMA block.
        // Writes slot (kt+3)&3 = (kt-1)&3, whose readers all passed the barrier
        // at the top of this iteration. Data needed 3 iterations from now.
        if (kt + NSTAGE - 1 < KITERS)
            loadStage((kt + NSTAGE - 1) & (NSTAGE - 1), kt + NSTAGE - 1);
        CP_COMMIT();         // unconditional: uniform group count for CP_WAIT(2)
    }

    // ---- epilogue: add bias, write fp32 ----
    const int g = lane >> 2;
    const int tig = lane & 3;
    const int gn0 = nt * TILE_N + n0w;
    float2 bb[4];
#pragma unroll
    for (int ni = 0; ni < 4; ni++)
        bb[ni] = *reinterpret_cast<const float2*>(bias + gn0 + ni * 8 + tig * 2);

    const size_t rowbase = (size_t)mt * TILE_M + m0w;
#pragma unroll
    for (int mi = 0; mi < 2; mi++) {
        size_t r0 = rowbase + mi * 16 + g;
        size_t r1 = r0 + 8;
#pragma unroll
        for (int ni = 0; ni < 4; ni++) {
            float* p0 = out + r0 * (size_t)V_ + gn0 + ni * 8 + tig * 2;
            float* p1 = out + r1 * (size_t)V_ + gn0 + ni * 8 + tig * 2;
            *reinterpret_cast<float2*>(p0) =
                make_float2(acc[mi][ni][0] + bb[ni].x, acc[mi][ni][1] + bb[ni].y);
            *reinterpret_cast<float2*>(p1) =
                make_float2(acc[mi][ni][2] + bb[ni].x, acc[mi][ni][3] + bb[ni].y);
        }
    }
}

extern "C" void kernel_launch(void* const* d_in, const int* in_sizes, int n_in,
                              void* d_out, int out_size) {
    const float* src  = (const float*)d_in[0];
    const int*   slen = (const int*)d_in[1];
    const float* tgt  = (const float*)d_in[2];
    const int*   tlen = (const int*)d_in[3];
    const float* W    = (const float*)d_in[4];
    const float* bias = (const float*)d_in[5];
    float* out = (float*)d_out;

    long long main_elems = (long long)M_ * V_;
    int ntail = 0;
    if ((long long)out_size > main_elems) {
        ntail = (int)((long long)out_size - main_elems);
        if (ntail > 32) ntail = 32;
    }
    prep_kernel<<<(V_ * D_ / 4) / 256, 256>>>(W, slen, tlen, out + main_elems, ntail);
    build_A<<<((size_t)M_ * D_ / 8) / 256, 256>>>(src, tgt);

    cudaFuncSetAttribute(joiner_gemm, cudaFuncAttributeMaxDynamicSharedMemorySize, SMEM_DYN);
    dim3 grid(V_ / TILE_N, M_ / TILE_M);  // (8, 512) nt-fast
    joiner_gemm<<<grid, NTHREADS, SMEM_DYN>>>(bias, out);
}

// round 15
// speedup vs baseline: 1.0804x; 1.0804x over previous
#include <cuda_runtime.h>
#include <cuda_fp16.h>
#include <cstdint>

// ---------------------------------------------------------------------------
// RNNT joiner, two-pass (R7/R13 frozen config; R15 = epilogue-only change):
//   pass 1: Ah[m][d] = fp16(relu(src[b,t,d] + tgt[b,u,d]))
//   pass 2: out = Ah @ Wh^T + bias  (M=65536, N=1024, K=1024, HMMA fp16)
// GEMM: 512 thr, 16 warps (4m x 4n of 32x32), CTA 128x128x32, 4-stage
// cp.async, PITCH=80, 2 CTAs/SM (32 warps), nt-fast grid.
// Seven deviations regressed (fusion, TILE_K=64 x2, NSTAGE, unroll/reorder,
// build_A widening, late prefetch). Mainloop is frozen.
// R15: output stores use __stcs (evict-first streaming) so the 256MB write
// stream stops evicting the L2-shared A tiles (8-way nt reuse) and W.
// ---------------------------------------------------------------------------

#define B_ 4
#define T_ 256
#define U_ 64
#define D_ 1024
#define V_ 1024
#define M_ (B_ * T_ * U_)

#define TILE_M 128
#define TILE_N 128
#define TILE_K 32
#define KITERS (D_ / TILE_K) /* 32 */
#define NTHREADS 512
#define NSTAGE 4

#define PITCH 80                      /* 64B row + 16B pad: conflict-free ldmatrix */
#define STAGE_BYTES (128 * PITCH)     /* 10240 */
#define SMEM_DYN (2 * NSTAGE * STAGE_BYTES) /* A[4] + B[4] = 81920 -> 2 CTAs/SM */

__device__ __forceinline__ uint32_t smem_u32(const void* p) {
    uint32_t a;
    asm("{ .reg .u64 t; cvta.to.shared.u64 t, %1; cvt.u32.u64 %0, t; }" : "=r"(a) : "l"(p));
    return a;
}

__device__ __forceinline__ void cp16(uint32_t saddr, const void* g) {
    asm volatile("cp.async.cg.shared.global [%0], [%1], 16;" :: "r"(saddr), "l"(g) : "memory");
}
#define CP_COMMIT() asm volatile("cp.async.commit_group;" ::: "memory")
#define CP_WAIT(n)  asm volatile("cp.async.wait_group %0;" :: "n"(n) : "memory")

__device__ __forceinline__ void ldsm_x4(uint32_t (&r)[4], uint32_t addr) {
    asm volatile("ldmatrix.sync.aligned.m8n8.x4.shared.b16 {%0,%1,%2,%3}, [%4];"
                 : "=r"(r[0]), "=r"(r[1]), "=r"(r[2]), "=r"(r[3]) : "r"(addr));
}

__device__ __forceinline__ void mma16816(float (&d)[4], const uint32_t (&a)[4],
                                         uint32_t b0, uint32_t b1) {
    asm volatile(
        "mma.sync.aligned.m16n8k16.row.col.f32.f16.f16.f32 "
        "{%0,%1,%2,%3}, {%4,%5,%6,%7}, {%8,%9}, {%0,%1,%2,%3};"
        : "+f"(d[0]), "+f"(d[1]), "+f"(d[2]), "+f"(d[3])
        : "r"(a[0]), "r"(a[1]), "r"(a[2]), "r"(a[3]), "r"(b0), "r"(b1));
}

__device__ __forceinline__ uint32_t h2u(__half2 h) { return *reinterpret_cast<uint32_t*>(&h); }

// Static scratch: W in fp16 (2 MB) and the materialized A operand (128 MB fp16).
__device__ __align__(16) __half g_Wh[(size_t)V_ * D_];
__device__ __align__(16) __half g_Ah[(size_t)M_ * D_];

// convert W + write the appended lengths tail
__global__ void __launch_bounds__(256) prep_kernel(
    const float* __restrict__ W,
    const int* __restrict__ sl, const int* __restrict__ tl,
    float* __restrict__ tail_out, int ntail) {
    int i = blockIdx.x * blockDim.x + threadIdx.x;  // over V*D/4
    float4 v = reinterpret_cast<const float4*>(W)[i];
    __half2* dst = reinterpret_cast<__half2*>(g_Wh);
    dst[2 * i + 0] = __floats2half2_rn(v.x, v.y);
    dst[2 * i + 1] = __floats2half2_rn(v.z, v.w);
    if (blockIdx.x == 0 && threadIdx.x < (unsigned)ntail) {
        int k = threadIdx.x;
        int val = (k < B_) ? sl[k] : ((k < 2 * B_) ? tl[k - B_] : 0);
        tail_out[k] = (float)val;
    }
}

// pass 1: Ah = fp16(relu(src+tgt)); 8 elements per thread (coalesced 16B/lane)
__global__ void __launch_bounds__(256) build_A(const float* __restrict__ src,
                                               const float* __restrict__ tgt) {
    size_t i = (size_t)blockIdx.x * blockDim.x + threadIdx.x;  // over M*D/8
    int dc = (int)(i & (D_ / 8 - 1)) * 8;
    size_t row = i >> 7;
    int u = (int)(row & (U_ - 1));
    int t = (int)((row >> 6) & (T_ - 1));
    int b = (int)(row >> 14);
    const float4* sp = reinterpret_cast<const float4*>(src + ((size_t)(b * T_ + t)) * D_ + dc);
    const float4* tp = reinterpret_cast<const float4*>(tgt + ((size_t)(b * U_ + u)) * D_ + dc);
    float4 s0 = sp[0], s1 = sp[1];
    float4 g0 = tp[0], g1 = tp[1];
    __half2 h0 = __floats2half2_rn(fmaxf(s0.x + g0.x, 0.f), fmaxf(s0.y + g0.y, 0.f));
    __half2 h1 = __floats2half2_rn(fmaxf(s0.z + g0.z, 0.f), fmaxf(s0.w + g0.w, 0.f));
    __half2 h2 = __floats2half2_rn(fmaxf(s1.x + g1.x, 0.f), fmaxf(s1.y + g1.y, 0.f));
    __half2 h3 = __floats2half2_rn(fmaxf(s1.z + g1.z, 0.f), fmaxf(s1.w + g1.w, 0.f));
    *reinterpret_cast<uint4*>(g_Ah + row * D_ + dc) =
        make_uint4(h2u(h0), h2u(h1), h2u(h2), h2u(h3));
}

__global__ void __launch_bounds__(NTHREADS, 2) joiner_gemm(
    const float* __restrict__ bias, float* __restrict__ out) {
    extern __shared__ __align__(128) char smem[];
    const uint32_t A0 = smem_u32(smem);
    const uint32_t Bb0 = A0 + NSTAGE * STAGE_BYTES;

    const int tid = threadIdx.x;
    const int wid = tid >> 5, lane = tid & 31;
    const int nt = blockIdx.x;   // 0..7   (nt-fast: 8 CTAs share one A tile in L2)
    const int mt = blockIdx.y;   // 0..511

    // ---- load-role: thread -> (row = tid>>2, seg = tid&3); 1 cp16 per tile ----
    const int lrow = tid >> 2;
    const int lseg = tid & 3;
    const __half* arow = g_Ah + ((size_t)(mt * TILE_M + lrow)) * D_ + lseg * 8;
    const __half* wrow = g_Wh + ((size_t)(nt * TILE_N + lrow)) * D_ + lseg * 8;
    const uint32_t fill_off = (uint32_t)lrow * PITCH + lseg * 16;

    // ---- mma-role: 16 warps = 4m x 4n, warp tile 32x32 ----
    const int m0w = (wid & 3) * 32;
    const int n0w = (wid >> 2) * 32;
    const uint32_t a_ld_off = (uint32_t)(m0w + (lane & 15)) * PITCH + (lane >> 4) * 16;
    const uint32_t b_ld_off =
        (uint32_t)(n0w + (lane & 7) + ((lane & 16) >> 1)) * PITCH + ((lane >> 3) & 1) * 16;

    float acc[2][4][4];
#pragma unroll
    for (int mi = 0; mi < 2; mi++)
#pragma unroll
        for (int ni = 0; ni < 4; ni++)
#pragma unroll
            for (int q = 0; q < 4; q++) acc[mi][ni][q] = 0.f;

    auto loadStage = [&](int s, int kt) {
        cp16(A0 + s * STAGE_BYTES + fill_off, arow + kt * TILE_K);
        cp16(Bb0 + s * STAGE_BYTES + fill_off, wrow + kt * TILE_K);
    };

    // prologue: stages 0,1,2 in flight
#pragma unroll
    for (int s = 0; s < NSTAGE - 1; s++) {
        loadStage(s, s);
        CP_COMMIT();
    }

#pragma unroll 1
    for (int kt = 0; kt < KITERS; kt++) {
        const int cur = kt & (NSTAGE - 1);
        CP_WAIT(2);          // stage `cur` complete
        __syncthreads();
        if (kt + NSTAGE - 1 < KITERS)
            loadStage((kt + NSTAGE - 1) & (NSTAGE - 1), kt + NSTAGE - 1);
        CP_COMMIT();

        const uint32_t Ab = A0 + cur * STAGE_BYTES;
        const uint32_t Bt = Bb0 + cur * STAGE_BYTES;
#pragma unroll
        for (int k16 = 0; k16 < 2; k16++) {
            const uint32_t kb = k16 * 32;
            uint32_t bfr[2][4];
            ldsm_x4(bfr[0], Bt + b_ld_off + kb);
            ldsm_x4(bfr[1], Bt + 16u * PITCH + b_ld_off + kb);
            uint32_t afr[2][4];
            ldsm_x4(afr[0], Ab + a_ld_off + kb);
            ldsm_x4(afr[1], Ab + 16u * PITCH + a_ld_off + kb);
#pragma unroll
            for (int mi = 0; mi < 2; mi++)
#pragma unroll
                for (int ni = 0; ni < 4; ni++)
                    mma16816(acc[mi][ni], afr[mi], bfr[ni >> 1][(ni & 1) * 2],
                             bfr[ni >> 1][(ni & 1) * 2 + 1]);
        }
    }

    // ---- epilogue: add bias, write fp32 with streaming (evict-first) stores ----
    const int g = lane >> 2;
    const int tig = lane & 3;
    const int gn0 = nt * TILE_N + n0w;
    float2 bb[4];
#pragma unroll
    for (int ni = 0; ni < 4; ni++)
        bb[ni] = *reinterpret_cast<const float2*>(bias + gn0 + ni * 8 + tig * 2);

    const size_t rowbase = (size_t)mt * TILE_M + m0w;
#pragma unroll
    for (int mi = 0; mi < 2; mi++) {
        size_t r0 = rowbase + mi * 16 + g;
        size_t r1 = r0 + 8;
#pragma unroll
        for (int ni = 0; ni < 4; ni++) {
            float2* p0 = reinterpret_cast<float2*>(out + r0 * (size_t)V_ + gn0 + ni * 8 + tig * 2);
            float2* p1 = reinterpret_cast<float2*>(out + r1 * (size_t)V_ + gn0 + ni * 8 + tig * 2);
            __stcs(p0, make_float2(acc[mi][ni][0] + bb[ni].x, acc[mi][ni][1] + bb[ni].y));
            __stcs(p1, make_float2(acc[mi][ni][2] + bb[ni].x, acc[mi][ni][3] + bb[ni].y));
        }
    }
}

extern "C" void kernel_launch(void* const* d_in, const int* in_sizes, int n_in,
                              void* d_out, int out_size) {
    const float* src  = (const float*)d_in[0];
    const int*   slen = (const int*)d_in[1];
    const float* tgt  = (const float*)d_in[2];
    const int*   tlen = (const int*)d_in[3];
    const float* W    = (const float*)d_in[4];
    const float* bias = (const float*)d_in[5];
    float* out = (float*)d_out;

    long long main_elems = (long long)M_ * V_;
    int ntail = 0;
    if ((long long)out_size > main_elems) {
        ntail = (int)((long long)out_size - main_elems);
        if (ntail > 32) ntail = 32;
    }
    prep_kernel<<<(V_ * D_ / 4) / 256, 256>>>(W, slen, tlen, out + main_elems, ntail);
    build_A<<<((size_t)M_ * D_ / 8) / 256, 256>>>(src, tgt);

    cudaFuncSetAttribute(joiner_gemm, cudaFuncAttributeMaxDynamicSharedMemorySize, SMEM_DYN);
    dim3 grid(V_ / TILE_N, M_ / TILE_M);  // (8, 512) nt-fast
    joiner_gemm<<<grid, NTHREADS, SMEM_DYN>>>(bias, out);
}

// round 17
// speedup vs baseline: 1.0810x; 1.0006x over previous
#include <cuda_runtime.h>
#include <cuda_fp16.h>
#include <cstdint>

// ---------------------------------------------------------------------------
// RNNT joiner, two-pass (R15 frozen + R17 aux-only change):
//   pass 1: Ah[m][d] = fp16(relu(src[b,t,d] + tgt[b,u,d]))
//   pass 2: out = Ah @ Wh^T + bias  (M=65536, N=1024, K=1024, HMMA fp16)
// GEMM: 512 thr, 16 warps (4m x 4n of 32x32), CTA 128x128x32, 4-stage
// cp.async, PITCH=80, 2 CTAs/SM (32 warps), nt-fast grid, __stcs epilogue.
// Mainloop frozen (8 perturbations regressed). Multi-stream overlap is
// blocked by the harness's allocation guard (R16).
// R17: build_A's 128MB write stream also uses __stcs (write-once, never
// L2-resident before its consumer kernel) to cut L2 churn.
// ---------------------------------------------------------------------------

#define B_ 4
#define T_ 256
#define U_ 64
#define D_ 1024
#define V_ 1024
#define M_ (B_ * T_ * U_)

#define TILE_M 128
#define TILE_N 128
#define TILE_K 32
#define KITERS (D_ / TILE_K) /* 32 */
#define NTHREADS 512
#define NSTAGE 4

#define PITCH 80                      /* 64B row + 16B pad: conflict-free ldmatrix */
#define STAGE_BYTES (128 * PITCH)     /* 10240 */
#define SMEM_DYN (2 * NSTAGE * STAGE_BYTES) /* A[4] + B[4] = 81920 -> 2 CTAs/SM */

__device__ __forceinline__ uint32_t smem_u32(const void* p) {
    uint32_t a;
    asm("{ .reg .u64 t; cvta.to.shared.u64 t, %1; cvt.u32.u64 %0, t; }" : "=r"(a) : "l"(p));
    return a;
}

__device__ __forceinline__ void cp16(uint32_t saddr, const void* g) {
    asm volatile("cp.async.cg.shared.global [%0], [%1], 16;" :: "r"(saddr), "l"(g) : "memory");
}
#define CP_COMMIT() asm volatile("cp.async.commit_group;" ::: "memory")
#define CP_WAIT(n)  asm volatile("cp.async.wait_group %0;" :: "n"(n) : "memory")

__device__ __forceinline__ void ldsm_x4(uint32_t (&r)[4], uint32_t addr) {
    asm volatile("ldmatrix.sync.aligned.m8n8.x4.shared.b16 {%0,%1,%2,%3}, [%4];"
                 : "=r"(r[0]), "=r"(r[1]), "=r"(r[2]), "=r"(r[3]) : "r"(addr));
}

__device__ __forceinline__ void mma16816(float (&d)[4], const uint32_t (&a)[4],
                                         uint32_t b0, uint32_t b1) {
    asm volatile(
        "mma.sync.aligned.m16n8k16.row.col.f32.f16.f16.f32 "
        "{%0,%1,%2,%3}, {%4,%5,%6,%7}, {%8,%9}, {%0,%1,%2,%3};"
        : "+f"(d[0]), "+f"(d[1]), "+f"(d[2]), "+f"(d[3])
        : "r"(a[0]), "r"(a[1]), "r"(a[2]), "r"(a[3]), "r"(b0), "r"(b1));
}

__device__ __forceinline__ uint32_t h2u(__half2 h) { return *reinterpret_cast<uint32_t*>(&h); }

// Static scratch: W in fp16 (2 MB) and the materialized A operand (128 MB fp16).
__device__ __align__(16) __half g_Wh[(size_t)V_ * D_];
__device__ __align__(16) __half g_Ah[(size_t)M_ * D_];

// convert W + write the appended lengths tail
__global__ void __launch_bounds__(256) prep_kernel(
    const float* __restrict__ W,
    const int* __restrict__ sl, const int* __restrict__ tl,
    float* __restrict__ tail_out, int ntail) {
    int i = blockIdx.x * blockDim.x + threadIdx.x;  // over V*D/4
    float4 v = reinterpret_cast<const float4*>(W)[i];
    __half2* dst = reinterpret_cast<__half2*>(g_Wh);
    dst[2 * i + 0] = __floats2half2_rn(v.x, v.y);
    dst[2 * i + 1] = __floats2half2_rn(v.z, v.w);
    if (blockIdx.x == 0 && threadIdx.x < (unsigned)ntail) {
        int k = threadIdx.x;
        int val = (k < B_) ? sl[k] : ((k < 2 * B_) ? tl[k - B_] : 0);
        tail_out[k] = (float)val;
    }
}

// pass 1: Ah = fp16(relu(src+tgt)); 8 elems/thread, coalesced 16B/lane,
// streaming (evict-first) stores — written once, consumed next kernel.
__global__ void __launch_bounds__(256) build_A(const float* __restrict__ src,
                                               const float* __restrict__ tgt) {
    size_t i = (size_t)blockIdx.x * blockDim.x + threadIdx.x;  // over M*D/8
    int dc = (int)(i & (D_ / 8 - 1)) * 8;
    size_t row = i >> 7;
    int u = (int)(row & (U_ - 1));
    int t = (int)((row >> 6) & (T_ - 1));
    int b = (int)(row >> 14);
    const float4* sp = reinterpret_cast<const float4*>(src + ((size_t)(b * T_ + t)) * D_ + dc);
    const float4* tp = reinterpret_cast<const float4*>(tgt + ((size_t)(b * U_ + u)) * D_ + dc);
    float4 s0 = sp[0], s1 = sp[1];
    float4 g0 = tp[0], g1 = tp[1];
    uint4 o;
    o.x = h2u(__floats2half2_rn(fmaxf(s0.x + g0.x, 0.f), fmaxf(s0.y + g0.y, 0.f)));
    o.y = h2u(__floats2half2_rn(fmaxf(s0.z + g0.z, 0.f), fmaxf(s0.w + g0.w, 0.f)));
    o.z = h2u(__floats2half2_rn(fmaxf(s1.x + g1.x, 0.f), fmaxf(s1.y + g1.y, 0.f)));
    o.w = h2u(__floats2half2_rn(fmaxf(s1.z + g1.z, 0.f), fmaxf(s1.w + g1.w, 0.f)));
    __stcs(reinterpret_cast<uint4*>(g_Ah + row * D_ + dc), o);
}

__global__ void __launch_bounds__(NTHREADS, 2) joiner_gemm(
    const float* __restrict__ bias, float* __restrict__ out) {
    extern __shared__ __align__(128) char smem[];
    const uint32_t A0 = smem_u32(smem);
    const uint32_t Bb0 = A0 + NSTAGE * STAGE_BYTES;

    const int tid = threadIdx.x;
    const int wid = tid >> 5, lane = tid & 31;
    const int nt = blockIdx.x;   // 0..7   (nt-fast: 8 CTAs share one A tile in L2)
    const int mt = blockIdx.y;   // 0..511

    // ---- load-role: thread -> (row = tid>>2, seg = tid&3); 1 cp16 per tile ----
    const int lrow = tid >> 2;
    const int lseg = tid & 3;
    const __half* arow = g_Ah + ((size_t)(mt * TILE_M + lrow)) * D_ + lseg * 8;
    const __half* wrow = g_Wh + ((size_t)(nt * TILE_N + lrow)) * D_ + lseg * 8;
    const uint32_t fill_off = (uint32_t)lrow * PITCH + lseg * 16;

    // ---- mma-role: 16 warps = 4m x 4n, warp tile 32x32 ----
    const int m0w = (wid & 3) * 32;
    const int n0w = (wid >> 2) * 32;
    const uint32_t a_ld_off = (uint32_t)(m0w + (lane & 15)) * PITCH + (lane >> 4) * 16;
    const uint32_t b_ld_off =
        (uint32_t)(n0w + (lane & 7) + ((lane & 16) >> 1)) * PITCH + ((lane >> 3) & 1) * 16;

    float acc[2][4][4];
#pragma unroll
    for (int mi = 0; mi < 2; mi++)
#pragma unroll
        for (int ni = 0; ni < 4; ni++)
#pragma unroll
            for (int q = 0; q < 4; q++) acc[mi][ni][q] = 0.f;

    auto loadStage = [&](int s, int kt) {
        cp16(A0 + s * STAGE_BYTES + fill_off, arow + kt * TILE_K);
        cp16(Bb0 + s * STAGE_BYTES + fill_off, wrow + kt * TILE_K);
    };

    // prologue: stages 0,1,2 in flight
#pragma unroll
    for (int s = 0; s < NSTAGE - 1; s++) {
        loadStage(s, s);
        CP_COMMIT();
    }

#pragma unroll 1
    for (int kt = 0; kt < KITERS; kt++) {
        const int cur = kt & (NSTAGE - 1);
        CP_WAIT(2);          // stage `cur` complete
        __syncthreads();
        if (kt + NSTAGE - 1 < KITERS)
            loadStage((kt + NSTAGE - 1) & (NSTAGE - 1), kt + NSTAGE - 1);
        CP_COMMIT();

        const uint32_t Ab = A0 + cur * STAGE_BYTES;
        const uint32_t Bt = Bb0 + cur * STAGE_BYTES;
#pragma unroll
        for (int k16 = 0; k16 < 2; k16++) {
            const uint32_t kb = k16 * 32;
            uint32_t bfr[2][4];
            ldsm_x4(bfr[0], Bt + b_ld_off + kb);
            ldsm_x4(bfr[1], Bt + 16u * PITCH + b_ld_off + kb);
            uint32_t afr[2][4];
            ldsm_x4(afr[0], Ab + a_ld_off + kb);
            ldsm_x4(afr[1], Ab + 16u * PITCH + a_ld_off + kb);
#pragma unroll
            for (int mi = 0; mi < 2; mi++)
#pragma unroll
                for (int ni = 0; ni < 4; ni++)
                    mma16816(acc[mi][ni], afr[mi], bfr[ni >> 1][(ni & 1) * 2],
                             bfr[ni >> 1][(ni & 1) * 2 + 1]);
        }
    }

    // ---- epilogue: add bias, write fp32 with streaming (evict-first) stores ----
    const int g = lane >> 2;
    const int tig = lane & 3;
    const int gn0 = nt * TILE_N + n0w;
    float2 bb[4];
#pragma unroll
    for (int ni = 0; ni < 4; ni++)
        bb[ni] = *reinterpret_cast<const float2*>(bias + gn0 + ni * 8 + tig * 2);

    const size_t rowbase = (size_t)mt * TILE_M + m0w;
#pragma unroll
    for (int mi = 0; mi < 2; mi++) {
        size_t r0 = rowbase + mi * 16 + g;
        size_t r1 = r0 + 8;
#pragma unroll
        for (int ni = 0; ni < 4; ni++) {
            float2* p0 = reinterpret_cast<float2*>(out + r0 * (size_t)V_ + gn0 + ni * 8 + tig * 2);
            float2* p1 = reinterpret_cast<float2*>(out + r1 * (size_t)V_ + gn0 + ni * 8 + tig * 2);
            __stcs(p0, make_float2(acc[mi][ni][0] + bb[ni].x, acc[mi][ni][1] + bb[ni].y));
            __stcs(p1, make_float2(acc[mi][ni][2] + bb[ni].x, acc[mi][ni][3] + bb[ni].y));
        }
    }
}

extern "C" void kernel_launch(void* const* d_in, const int* in_sizes, int n_in,
                              void* d_out, int out_size) {
    const float* src  = (const float*)d_in[0];
    const int*   slen = (const int*)d_in[1];
    const float* tgt  = (const float*)d_in[2];
    const int*   tlen = (const int*)d_in[3];
    const float* W    = (const float*)d_in[4];
    const float* bias = (const float*)d_in[5];
    float* out = (float*)d_out;

    long long main_elems = (long long)M_ * V_;
    int ntail = 0;
    if ((long long)out_size > main_elems) {
        ntail = (int)((long long)out_size - main_elems);
        if (ntail > 32) ntail = 32;
    }
    prep_kernel<<<(V_ * D_ / 4) / 256, 256>>>(W, slen, tlen, out + main_elems, ntail);
    build_A<<<((size_t)M_ * D_ / 8) / 256, 256>>>(src, tgt);

    cudaFuncSetAttribute(joiner_gemm, cudaFuncAttributeMaxDynamicSharedMemorySize, SMEM_DYN);
    dim3 grid(V_ / TILE_N, M_ / TILE_M);  // (8, 512) nt-fast
    joiner_gemm<<<grid, NTHREADS, SMEM_DYN>>>(bias, out);
}